// round 1
// baseline (speedup 1.0000x reference)
#include <cuda_runtime.h>

#define B_  2
#define S_  2048
#define D_  1024
#define H_  16
#define DH_ 64

// Scratch (device globals — no allocation allowed)
__device__ float g_Qh[(size_t)B_ * H_ * S_ * DH_];   // [B,H,S,DH]
__device__ float g_ctx[(size_t)B_ * S_ * D_];        // [B,S,D]

// ----------------------------------------------------------------------------
// SGEMM: out[m,n] = X[4096,1024] @ W[1024,1024] + bias[n]
// Epilogue scatter: m=(b,s), n=(h,d); idx = b*sB + s*sS + h*sH + d
// ----------------------------------------------------------------------------
__global__ __launch_bounds__(256) void gemm_kernel(
    const float* __restrict__ X, const float* __restrict__ W,
    const float* __restrict__ bias, float* __restrict__ out,
    long sB, long sS, long sH)
{
    __shared__ __align__(16) float As[16 * 128];  // transposed: As[k][m]
    __shared__ __align__(16) float Bs[16 * 128];  // natural:    Bs[k][n]

    const int tid = threadIdx.x;
    const int tx = tid & 15, ty = tid >> 4;
    const int m0 = blockIdx.y * 128, n0 = blockIdx.x * 128;

    float acc[8][8] = {};

    for (int k0 = 0; k0 < 1024; k0 += 16) {
        #pragma unroll
        for (int t = 0; t < 2; t++) {
            int idx = tid + t * 256;                 // 0..511
            // A tile: 128 rows x 16 cols, load float4, store transposed
            int r = idx >> 2, c4 = (idx & 3) << 2;
            float4 a = *(const float4*)(X + (size_t)(m0 + r) * 1024 + k0 + c4);
            As[(c4 + 0) * 128 + r] = a.x;
            As[(c4 + 1) * 128 + r] = a.y;
            As[(c4 + 2) * 128 + r] = a.z;
            As[(c4 + 3) * 128 + r] = a.w;
            // B tile: 16 rows x 128 cols, direct float4 copy
            int kk = idx >> 5, c = (idx & 31) << 2;
            *(float4*)(Bs + kk * 128 + c) =
                *(const float4*)(W + (size_t)(k0 + kk) * 1024 + n0 + c);
        }
        __syncthreads();

        #pragma unroll
        for (int kk = 0; kk < 16; kk++) {
            float a[8], b[8];
            *(float4*)(a)     = *(float4*)(As + kk * 128 + ty * 8);
            *(float4*)(a + 4) = *(float4*)(As + kk * 128 + ty * 8 + 4);
            *(float4*)(b)     = *(float4*)(Bs + kk * 128 + tx * 8);
            *(float4*)(b + 4) = *(float4*)(Bs + kk * 128 + tx * 8 + 4);
            #pragma unroll
            for (int i = 0; i < 8; i++)
                #pragma unroll
                for (int j = 0; j < 8; j++)
                    acc[i][j] += a[i] * b[j];
        }
        __syncthreads();
    }

    #pragma unroll
    for (int i = 0; i < 8; i++) {
        int m = m0 + ty * 8 + i;
        int b = m >> 11;           // m / S
        int s = m & 2047;          // m % S
        #pragma unroll
        for (int j = 0; j < 8; j++) {
            int n = n0 + tx * 8 + j;
            int h = n >> 6, d = n & 63;
            out[(long)b * sB + (long)s * sS + (long)h * sH + d] = acc[i][j] + bias[n];
        }
    }
}

// ----------------------------------------------------------------------------
// Flash attention (fp32, causal). One block = 64 queries of one (b,h).
// smem tiles padded to stride 65 where the fast axis is the thread axis.
// ----------------------------------------------------------------------------
__global__ __launch_bounds__(256) void attn_kernel(
    const float* __restrict__ present, float* __restrict__ ctx_out)
{
    extern __shared__ float sm[];
    float* Qt    = sm;              // [64][65]  Qt[d*65 + r]
    float* Kt    = Qt + 64 * 65;    // [64][65]  Kt[d*65 + c]
    float* Pt    = Kt + 64 * 65;    // [64][65]  Pt[c*65 + r]
    float* Vs    = Pt + 64 * 65;    // [64][64]  Vs[c*64 + d]
    float* rowm  = Vs + 64 * 64;    // [64]
    float* rowl  = rowm + 64;       // [64]
    float* alpha = rowl + 64;       // [64]

    const int tid = threadIdx.x;
    const int tx = tid & 15, ty = tid >> 4;
    const int qblk = blockIdx.x, h = blockIdx.y, b = blockIdx.z;
    const int q0 = qblk * 64;

    const float* Qbase = g_Qh + ((size_t)(b * H_ + h) * S_ + q0) * DH_;
    const float* Kbase = present + ((size_t)(b * 2 + 0) * H_ + h) * (size_t)S_ * DH_;
    const float* Vbase = present + ((size_t)(b * 2 + 1) * H_ + h) * (size_t)S_ * DH_;

    // Load Q transposed (once)
    #pragma unroll
    for (int t = 0; t < 16; t++) {
        int idx = tid + t * 256;
        int r = idx >> 6, d = idx & 63;
        Qt[d * 65 + r] = Qbase[idx];
    }
    if (tid < 64) { rowm[tid] = -1e30f; rowl[tid] = 0.f; }

    float o[4][4] = {};

    for (int kt = 0; kt <= qblk; kt++) {
        const int k0 = kt * 64;
        __syncthreads();  // previous iteration done reading Pt/Vs; Qt/rowm visible
        #pragma unroll
        for (int t = 0; t < 16; t++) {
            int idx = tid + t * 256;
            int c = idx >> 6, d = idx & 63;
            Kt[d * 65 + c] = Kbase[(size_t)(k0 + c) * 64 + d];
            Vs[c * 64 + d] = Vbase[(size_t)(k0 + c) * 64 + d];
        }
        __syncthreads();

        // S = Q K^T (4x4 per thread)
        float s[4][4] = {};
        for (int kk = 0; kk < 64; kk++) {
            float qv[4], kv[4];
            #pragma unroll
            for (int i = 0; i < 4; i++) qv[i] = Qt[kk * 65 + ty * 4 + i];
            #pragma unroll
            for (int j = 0; j < 4; j++) kv[j] = Kt[kk * 65 + tx * 4 + j];
            #pragma unroll
            for (int i = 0; i < 4; i++)
                #pragma unroll
                for (int j = 0; j < 4; j++)
                    s[i][j] += qv[i] * kv[j];
        }
        // scale + causal mask, write transposed scores
        #pragma unroll
        for (int i = 0; i < 4; i++) {
            int qi = q0 + ty * 4 + i;
            #pragma unroll
            for (int j = 0; j < 4; j++) {
                int kj = k0 + tx * 4 + j;
                float v = s[i][j] * 0.125f + (kj > qi ? -10000.f : 0.f);
                Pt[(tx * 4 + j) * 65 + (ty * 4 + i)] = v;
            }
        }
        __syncthreads();

        // Online softmax stats: 4 threads per row (lanes 4r..4r+3)
        {
            int r = tid >> 2, seg = tid & 3;
            float mx = -1e30f;
            #pragma unroll
            for (int t = 0; t < 16; t++)
                mx = fmaxf(mx, Pt[(seg * 16 + t) * 65 + r]);
            mx = fmaxf(mx, __shfl_xor_sync(0xffffffffu, mx, 1));
            mx = fmaxf(mx, __shfl_xor_sync(0xffffffffu, mx, 2));
            float mnew = fmaxf(rowm[r], mx);
            float sum = 0.f;
            #pragma unroll
            for (int t = 0; t < 16; t++) {
                int c = seg * 16 + t;
                float p = __expf(Pt[c * 65 + r] - mnew);
                Pt[c * 65 + r] = p;
                sum += p;
            }
            sum += __shfl_xor_sync(0xffffffffu, sum, 1);
            sum += __shfl_xor_sync(0xffffffffu, sum, 2);
            if (seg == 0) {
                float a = __expf(rowm[r] - mnew);
                alpha[r] = a;
                rowl[r] = rowl[r] * a + sum;
                rowm[r] = mnew;
            }
        }
        __syncthreads();

        // rescale accumulator + O += P V
        float av[4];
        #pragma unroll
        for (int i = 0; i < 4; i++) av[i] = alpha[ty * 4 + i];
        #pragma unroll
        for (int i = 0; i < 4; i++)
            #pragma unroll
            for (int j = 0; j < 4; j++)
                o[i][j] *= av[i];

        for (int kk = 0; kk < 64; kk++) {
            float pv[4], vv[4];
            #pragma unroll
            for (int i = 0; i < 4; i++) pv[i] = Pt[kk * 65 + ty * 4 + i];
            #pragma unroll
            for (int j = 0; j < 4; j++) vv[j] = Vs[kk * 64 + tx * 4 + j];
            #pragma unroll
            for (int i = 0; i < 4; i++)
                #pragma unroll
                for (int j = 0; j < 4; j++)
                    o[i][j] += pv[i] * vv[j];
        }
    }

    // normalize + write ctx [B,S,D] with D-index = h*64 + d
    #pragma unroll
    for (int i = 0; i < 4; i++) {
        int r = ty * 4 + i;
        float inv = 1.f / rowl[r];
        float4 ov;
        ov.x = o[i][0] * inv; ov.y = o[i][1] * inv;
        ov.z = o[i][2] * inv; ov.w = o[i][3] * inv;
        *(float4*)(ctx_out + (size_t)b * S_ * D_ + (size_t)(q0 + r) * D_ + h * 64 + tx * 4) = ov;
    }
}

// ----------------------------------------------------------------------------
extern "C" void kernel_launch(void* const* d_in, const int* in_sizes, int n_in,
                              void* d_out, int out_size)
{
    const float* q  = (const float*)d_in[0];
    const float* k  = (const float*)d_in[1];
    const float* v  = (const float*)d_in[2];
    // d_in[3] = mask (causal, handled analytically)
    const float* Wq = (const float*)d_in[4];
    const float* bq = (const float*)d_in[5];
    const float* Wk = (const float*)d_in[6];
    const float* bk = (const float*)d_in[7];
    const float* Wv = (const float*)d_in[8];
    const float* bv = (const float*)d_in[9];
    const float* Wo = (const float*)d_in[10];
    const float* bo = (const float*)d_in[11];

    float* out = (float*)d_out;                       // [B,S,D]
    float* present = out + (size_t)B_ * S_ * D_;      // [B,2,H,S,DH]

    float *Qh, *ctx;
    cudaGetSymbolAddress((void**)&Qh, g_Qh);
    cudaGetSymbolAddress((void**)&ctx, g_ctx);

    const long sB_head = (long)H_ * S_ * DH_;     // 2,097,152
    const long sH_head = (long)S_ * DH_;          // 131,072

    dim3 gg(8, 32);
    // Q -> g_Qh [B,H,S,DH]
    gemm_kernel<<<gg, 256>>>(q, Wq, bq, Qh, sB_head, (long)DH_, sH_head);
    // K -> present[:,0]  (b stride = 2*H*S*DH)
    gemm_kernel<<<gg, 256>>>(k, Wk, bk, present, 2 * sB_head, (long)DH_, sH_head);
    // V -> present[:,1]
    gemm_kernel<<<gg, 256>>>(v, Wv, bv, present + (size_t)sB_head, 2 * sB_head, (long)DH_, sH_head);

    const int smem = (3 * 64 * 65 + 64 * 64 + 3 * 64) * (int)sizeof(float);  // 67,072 B
    cudaFuncSetAttribute(attn_kernel, cudaFuncAttributeMaxDynamicSharedMemorySize, smem);
    attn_kernel<<<dim3(32, H_, B_), 256, smem>>>(present, ctx);

    // out = ctx @ Wo + bo   ([B,S,D] natural layout: sH=DH makes idx = m*D + n)
    gemm_kernel<<<gg, 256>>>(ctx, Wo, bo, out, (long)S_ * D_, (long)D_, (long)DH_);
}

// round 3
// speedup vs baseline: 1.6754x; 1.6754x over previous
#include <cuda_runtime.h>
#include <cuda_bf16.h>
#include <cstdint>

#define B_  2
#define S_  2048
#define D_  1024
#define H_  16
#define DH_ 64

// ---------------------------------------------------------------------------
// Scratch (device globals — no allocation allowed)
// ---------------------------------------------------------------------------
__device__ float g_Qh[(size_t)B_ * H_ * S_ * DH_];   // [B,H,S,DH]
__device__ float g_ctx[(size_t)B_ * S_ * D_];        // [B,S,D]
__device__ __nv_bfloat16 g_ahi[(size_t)4096 * 1024]; // bf16-hi of X  [M,K]
__device__ __nv_bfloat16 g_alo[(size_t)4096 * 1024]; // bf16-lo of X
__device__ __nv_bfloat16 g_bhi[(size_t)1024 * 1024]; // bf16-hi of W^T [N,K]
__device__ __nv_bfloat16 g_blo[(size_t)1024 * 1024]; // bf16-lo of W^T

// ---------------------------------------------------------------------------
__device__ __forceinline__ uint32_t smem_u32(const void* p) {
    uint32_t a;
    asm("{ .reg .u64 t; cvta.to.shared.u64 t, %1; cvt.u32.u64 %0, t; }" : "=r"(a) : "l"(p));
    return a;
}

#define LDMX4(r, addr) \
    asm volatile("ldmatrix.sync.aligned.m8n8.x4.shared.b16 {%0,%1,%2,%3}, [%4];" \
        : "=r"((r)[0]), "=r"((r)[1]), "=r"((r)[2]), "=r"((r)[3]) : "r"(addr))

#define MMA_BF16(d, a, b0, b1) \
    asm volatile("mma.sync.aligned.m16n8k16.row.col.f32.bf16.bf16.f32 " \
        "{%0,%1,%2,%3}, {%4,%5,%6,%7}, {%8,%9}, {%0,%1,%2,%3};" \
        : "+f"((d)[0]), "+f"((d)[1]), "+f"((d)[2]), "+f"((d)[3]) \
        : "r"((a)[0]), "r"((a)[1]), "r"((a)[2]), "r"((a)[3]), "r"(b0), "r"(b1))

#define CP_ASYNC16(sa, gp) \
    asm volatile("cp.async.cg.shared.global [%0], [%1], 16;" :: "r"(sa), "l"(gp))
#define CP_COMMIT() asm volatile("cp.async.commit_group;" ::: "memory")
#define CP_WAIT1()  asm volatile("cp.async.wait_group 1;" ::: "memory")
#define CP_WAIT0()  asm volatile("cp.async.wait_group 0;" ::: "memory")

// ---------------------------------------------------------------------------
// Prep: elementwise bf16 hi/lo split (X rows already K-major)
// ---------------------------------------------------------------------------
__global__ __launch_bounds__(256) void split_kernel(
    const float* __restrict__ x, __nv_bfloat16* __restrict__ hi,
    __nv_bfloat16* __restrict__ lo)
{
    int i = blockIdx.x * 256 + threadIdx.x;       // float4 index
    float4 v = ((const float4*)x)[i];
    __nv_bfloat16 h0 = __float2bfloat16(v.x);
    __nv_bfloat16 h1 = __float2bfloat16(v.y);
    __nv_bfloat16 h2 = __float2bfloat16(v.z);
    __nv_bfloat16 h3 = __float2bfloat16(v.w);
    __nv_bfloat162 hh0; hh0.x = h0; hh0.y = h1;
    __nv_bfloat162 hh1; hh1.x = h2; hh1.y = h3;
    __nv_bfloat162 ll0, ll1;
    ll0.x = __float2bfloat16(v.x - __bfloat162float(h0));
    ll0.y = __float2bfloat16(v.y - __bfloat162float(h1));
    ll1.x = __float2bfloat16(v.z - __bfloat162float(h2));
    ll1.y = __float2bfloat16(v.w - __bfloat162float(h3));
    ((__nv_bfloat162*)hi)[i * 2]     = hh0;
    ((__nv_bfloat162*)hi)[i * 2 + 1] = hh1;
    ((__nv_bfloat162*)lo)[i * 2]     = ll0;
    ((__nv_bfloat162*)lo)[i * 2 + 1] = ll1;
}

// Prep: transpose [K,N] -> [N,K] with bf16 split (W -> W^T hi/lo)
__global__ __launch_bounds__(256) void tsplit_kernel(
    const float* __restrict__ W, __nv_bfloat16* __restrict__ th,
    __nv_bfloat16* __restrict__ tl)
{
    __shared__ float ts[32][33];
    int tx = threadIdx.x & 31, ty = threadIdx.x >> 5;
    int kb = blockIdx.x * 32, nb = blockIdx.y * 32;
    #pragma unroll
    for (int j = 0; j < 4; j++)
        ts[ty + j * 8][tx] = W[(size_t)(kb + ty + j * 8) * 1024 + nb + tx];
    __syncthreads();
    #pragma unroll
    for (int j = 0; j < 4; j++) {
        int n = nb + ty + j * 8, k = kb + tx;
        float v = ts[tx][ty + j * 8];
        __nv_bfloat16 h = __float2bfloat16(v);
        th[(size_t)n * 1024 + k] = h;
        tl[(size_t)n * 1024 + k] = __float2bfloat16(v - __bfloat162float(h));
    }
}

// ---------------------------------------------------------------------------
// bf16x3 mma.sync GEMM: out = X[4096,1024] @ W[1024,1024] + bias
// A = X hi/lo [M,K], B = W^T hi/lo [N,K], both K-major bf16.
// CTA 128x128, K-tile 32, 8 warps (64x32 each), cp.async 2-stage pipeline.
// Epilogue scatter: m=(b,s), n=(h,d); idx = b*sB + s*sS + h*sH + d
// ---------------------------------------------------------------------------
#define SA_STRIDE 80                    // bytes/row (40 bf16, conflict-free ldmatrix)
#define MAT_BYTES (128 * SA_STRIDE)     // 10240
#define STG_BYTES (4 * MAT_BYTES)       // 40960: Ahi|Alo|Bhi|Blo
#define GEMM_SMEM (2 * STG_BYTES)       // 81920

__global__ __launch_bounds__(256) void gemm_mma_kernel(
    const __nv_bfloat16* __restrict__ Ahi, const __nv_bfloat16* __restrict__ Alo,
    const __nv_bfloat16* __restrict__ Bhi, const __nv_bfloat16* __restrict__ Blo,
    const float* __restrict__ bias, float* __restrict__ out,
    long sB, long sS, long sH)
{
    extern __shared__ char sm[];
    const uint32_t sbase = smem_u32(sm);
    const int tid = threadIdx.x, lane = tid & 31, wid = tid >> 5;
    const int wm = wid & 1, wn = wid >> 1;              // warp grid 2(M) x 4(N)
    const int m0 = blockIdx.y * 128, n0 = blockIdx.x * 128;

    float acc[4][4][4] = {};                            // [mf][nf][reg]

    // ldmatrix lane addressing (constant per thread)
    const int arow  = lane & 15;
    const int akoff = (lane >> 4) * 16;
    const int brow  = ((lane >> 4) << 3) | (lane & 7);
    const int bkoff = ((lane >> 3) & 1) * 16;

    // ---- async tile loader: 8 x 16B per thread per stage ----
    #define ISSUE(t) do { \
        const int k0i = (t) * 32; \
        const uint32_t sdst = sbase + ((t) & 1) * STG_BYTES; \
        _Pragma("unroll") \
        for (int i = 0; i < 8; i++) { \
            int idx = tid + i * 256; \
            int mat = idx >> 9, chunk = idx & 511; \
            int row = chunk >> 2, c = chunk & 3; \
            const __nv_bfloat16* gp; \
            if (mat == 0)      gp = Ahi + (size_t)(m0 + row) * 1024 + k0i + c * 8; \
            else if (mat == 1) gp = Alo + (size_t)(m0 + row) * 1024 + k0i + c * 8; \
            else if (mat == 2) gp = Bhi + (size_t)(n0 + row) * 1024 + k0i + c * 8; \
            else               gp = Blo + (size_t)(n0 + row) * 1024 + k0i + c * 8; \
            uint32_t sa = sdst + mat * MAT_BYTES + row * SA_STRIDE + c * 16; \
            CP_ASYNC16(sa, gp); \
        } \
        CP_COMMIT(); \
    } while (0)

    ISSUE(0);

    for (int t = 0; t < 32; t++) {
        if (t < 31) { ISSUE(t + 1); CP_WAIT1(); }
        else        { CP_WAIT0(); }
        __syncthreads();

        const uint32_t s0  = sbase + (t & 1) * STG_BYTES;
        const uint32_t pAh = s0;
        const uint32_t pAl = s0 + MAT_BYTES;
        const uint32_t pBh = s0 + 2 * MAT_BYTES;
        const uint32_t pBl = s0 + 3 * MAT_BYTES;

        #pragma unroll
        for (int ks = 0; ks < 2; ks++) {
            uint32_t ah[4][4], al[4][4];
            #pragma unroll
            for (int mf = 0; mf < 4; mf++) {
                uint32_t ra = (uint32_t)(wm * 64 + mf * 16 + arow) * SA_STRIDE + ks * 32 + akoff;
                LDMX4(ah[mf], pAh + ra);
                LDMX4(al[mf], pAl + ra);
            }
            uint32_t bh[2][4], bl[2][4];
            #pragma unroll
            for (int ng = 0; ng < 2; ng++) {
                uint32_t rb = (uint32_t)(wn * 32 + ng * 16 + brow) * SA_STRIDE + ks * 32 + bkoff;
                LDMX4(bh[ng], pBh + rb);
                LDMX4(bl[ng], pBl + rb);
            }
            #pragma unroll
            for (int mf = 0; mf < 4; mf++) {
                #pragma unroll
                for (int nf = 0; nf < 4; nf++) {
                    const uint32_t* bhp = &bh[nf >> 1][(nf & 1) * 2];
                    const uint32_t* blp = &bl[nf >> 1][(nf & 1) * 2];
                    MMA_BF16(acc[mf][nf], ah[mf], bhp[0], bhp[1]);
                    MMA_BF16(acc[mf][nf], ah[mf], blp[0], blp[1]);
                    MMA_BF16(acc[mf][nf], al[mf], bhp[0], bhp[1]);
                }
            }
        }
        __syncthreads();
    }

    // ---- epilogue: scatter with bias ----
    const int g = lane >> 2, tig = lane & 3;
    #pragma unroll
    for (int mf = 0; mf < 4; mf++) {
        const int mA = m0 + wm * 64 + mf * 16 + g;
        const int b1 = mA >> 11, s1 = mA & 2047;
        const int b2 = (mA + 8) >> 11, s2 = (mA + 8) & 2047;
        #pragma unroll
        for (int nf = 0; nf < 4; nf++) {
            const int n = n0 + wn * 32 + nf * 8 + tig * 2;
            const int h = n >> 6, d = n & 63;
            const float bv0 = __ldg(bias + n), bv1 = __ldg(bias + n + 1);
            float2 lo_pair, hi_pair;
            lo_pair.x = acc[mf][nf][0] + bv0; lo_pair.y = acc[mf][nf][1] + bv1;
            hi_pair.x = acc[mf][nf][2] + bv0; hi_pair.y = acc[mf][nf][3] + bv1;
            *(float2*)(out + (size_t)b1 * sB + (size_t)s1 * sS + (size_t)h * sH + d) = lo_pair;
            *(float2*)(out + (size_t)b2 * sB + (size_t)s2 * sS + (size_t)h * sH + d) = hi_pair;
        }
    }
    #undef ISSUE
}

// ---------------------------------------------------------------------------
// Flash attention (fp32, causal) — unchanged from R1
// ---------------------------------------------------------------------------
__global__ __launch_bounds__(256) void attn_kernel(
    const float* __restrict__ present, float* __restrict__ ctx_out)
{
    extern __shared__ float smf[];
    float* Qt    = smf;
    float* Kt    = Qt + 64 * 65;
    float* Pt    = Kt + 64 * 65;
    float* Vs    = Pt + 64 * 65;
    float* rowm  = Vs + 64 * 64;
    float* rowl  = rowm + 64;
    float* alpha = rowl + 64;

    const int tid = threadIdx.x;
    const int tx = tid & 15, ty = tid >> 4;
    const int qblk = blockIdx.x, h = blockIdx.y, b = blockIdx.z;
    const int q0 = qblk * 64;

    const float* Qbase = g_Qh + ((size_t)(b * H_ + h) * S_ + q0) * DH_;
    const float* Kbase = present + ((size_t)(b * 2 + 0) * H_ + h) * (size_t)S_ * DH_;
    const float* Vbase = present + ((size_t)(b * 2 + 1) * H_ + h) * (size_t)S_ * DH_;

    #pragma unroll
    for (int t = 0; t < 16; t++) {
        int idx = tid + t * 256;
        int r = idx >> 6, d = idx & 63;
        Qt[d * 65 + r] = Qbase[idx];
    }
    if (tid < 64) { rowm[tid] = -1e30f; rowl[tid] = 0.f; }

    float o[4][4] = {};

    for (int kt = 0; kt <= qblk; kt++) {
        const int k0 = kt * 64;
        __syncthreads();
        #pragma unroll
        for (int t = 0; t < 16; t++) {
            int idx = tid + t * 256;
            int c = idx >> 6, d = idx & 63;
            Kt[d * 65 + c] = Kbase[(size_t)(k0 + c) * 64 + d];
            Vs[c * 64 + d] = Vbase[(size_t)(k0 + c) * 64 + d];
        }
        __syncthreads();

        float s[4][4] = {};
        for (int kk = 0; kk < 64; kk++) {
            float qv[4], kv[4];
            #pragma unroll
            for (int i = 0; i < 4; i++) qv[i] = Qt[kk * 65 + ty * 4 + i];
            #pragma unroll
            for (int j = 0; j < 4; j++) kv[j] = Kt[kk * 65 + tx * 4 + j];
            #pragma unroll
            for (int i = 0; i < 4; i++)
                #pragma unroll
                for (int j = 0; j < 4; j++)
                    s[i][j] += qv[i] * kv[j];
        }
        #pragma unroll
        for (int i = 0; i < 4; i++) {
            int qi = q0 + ty * 4 + i;
            #pragma unroll
            for (int j = 0; j < 4; j++) {
                int kj = k0 + tx * 4 + j;
                float v = s[i][j] * 0.125f + (kj > qi ? -10000.f : 0.f);
                Pt[(tx * 4 + j) * 65 + (ty * 4 + i)] = v;
            }
        }
        __syncthreads();

        {
            int r = tid >> 2, seg = tid & 3;
            float mx = -1e30f;
            #pragma unroll
            for (int t = 0; t < 16; t++)
                mx = fmaxf(mx, Pt[(seg * 16 + t) * 65 + r]);
            mx = fmaxf(mx, __shfl_xor_sync(0xffffffffu, mx, 1));
            mx = fmaxf(mx, __shfl_xor_sync(0xffffffffu, mx, 2));
            float mnew = fmaxf(rowm[r], mx);
            float sum = 0.f;
            #pragma unroll
            for (int t = 0; t < 16; t++) {
                int c = seg * 16 + t;
                float p = __expf(Pt[c * 65 + r] - mnew);
                Pt[c * 65 + r] = p;
                sum += p;
            }
            sum += __shfl_xor_sync(0xffffffffu, sum, 1);
            sum += __shfl_xor_sync(0xffffffffu, sum, 2);
            if (seg == 0) {
                float a = __expf(rowm[r] - mnew);
                alpha[r] = a;
                rowl[r] = rowl[r] * a + sum;
                rowm[r] = mnew;
            }
        }
        __syncthreads();

        float av[4];
        #pragma unroll
        for (int i = 0; i < 4; i++) av[i] = alpha[ty * 4 + i];
        #pragma unroll
        for (int i = 0; i < 4; i++)
            #pragma unroll
            for (int j = 0; j < 4; j++)
                o[i][j] *= av[i];

        for (int kk = 0; kk < 64; kk++) {
            float pv[4], vv[4];
            #pragma unroll
            for (int i = 0; i < 4; i++) pv[i] = Pt[kk * 65 + ty * 4 + i];
            #pragma unroll
            for (int j = 0; j < 4; j++) vv[j] = Vs[kk * 64 + tx * 4 + j];
            #pragma unroll
            for (int i = 0; i < 4; i++)
                #pragma unroll
                for (int j = 0; j < 4; j++)
                    o[i][j] += pv[i] * vv[j];
        }
    }

    #pragma unroll
    for (int i = 0; i < 4; i++) {
        int r = ty * 4 + i;
        float inv = 1.f / rowl[r];
        float4 ov;
        ov.x = o[i][0] * inv; ov.y = o[i][1] * inv;
        ov.z = o[i][2] * inv; ov.w = o[i][3] * inv;
        *(float4*)(ctx_out + (size_t)b * S_ * D_ + (size_t)(q0 + r) * D_ + h * 64 + tx * 4) = ov;
    }
}

// ---------------------------------------------------------------------------
extern "C" void kernel_launch(void* const* d_in, const int* in_sizes, int n_in,
                              void* d_out, int out_size)
{
    const float* q  = (const float*)d_in[0];
    const float* k  = (const float*)d_in[1];
    const float* v  = (const float*)d_in[2];
    const float* Wq = (const float*)d_in[4];
    const float* bq = (const float*)d_in[5];
    const float* Wk = (const float*)d_in[6];
    const float* bk = (const float*)d_in[7];
    const float* Wv = (const float*)d_in[8];
    const float* bv = (const float*)d_in[9];
    const float* Wo = (const float*)d_in[10];
    const float* bo = (const float*)d_in[11];

    float* out = (float*)d_out;                       // [B,S,D]
    float* present = out + (size_t)B_ * S_ * D_;      // [B,2,H,S,DH]

    float *Qh, *ctx;
    __nv_bfloat16 *ahi, *alo, *bhi, *blo;
    cudaGetSymbolAddress((void**)&Qh,  g_Qh);
    cudaGetSymbolAddress((void**)&ctx, g_ctx);
    cudaGetSymbolAddress((void**)&ahi, g_ahi);
    cudaGetSymbolAddress((void**)&alo, g_alo);
    cudaGetSymbolAddress((void**)&bhi, g_bhi);
    cudaGetSymbolAddress((void**)&blo, g_blo);

    const long sB_head = (long)H_ * S_ * DH_;     // 2,097,152
    const long sH_head = (long)S_ * DH_;          // 131,072

    cudaFuncSetAttribute(gemm_mma_kernel, cudaFuncAttributeMaxDynamicSharedMemorySize, GEMM_SMEM);

    const int nsplit = (4096 * 1024 / 4) / 256;   // 4096 blocks
    dim3 tgrid(32, 32), ggrid(8, 32);

    // Q projection -> g_Qh [B,H,S,DH]
    split_kernel<<<nsplit, 256>>>(q, ahi, alo);
    tsplit_kernel<<<tgrid, 256>>>(Wq, bhi, blo);
    gemm_mma_kernel<<<ggrid, 256, GEMM_SMEM>>>(ahi, alo, bhi, blo, bq, Qh,
                                               sB_head, (long)DH_, sH_head);
    // K projection -> present[:,0]
    split_kernel<<<nsplit, 256>>>(k, ahi, alo);
    tsplit_kernel<<<tgrid, 256>>>(Wk, bhi, blo);
    gemm_mma_kernel<<<ggrid, 256, GEMM_SMEM>>>(ahi, alo, bhi, blo, bk, present,
                                               2 * sB_head, (long)DH_, sH_head);
    // V projection -> present[:,1]
    split_kernel<<<nsplit, 256>>>(v, ahi, alo);
    tsplit_kernel<<<tgrid, 256>>>(Wv, bhi, blo);
    gemm_mma_kernel<<<ggrid, 256, GEMM_SMEM>>>(ahi, alo, bhi, blo, bv, present + (size_t)sB_head,
                                               2 * sB_head, (long)DH_, sH_head);

    // attention
    const int asmem = (3 * 64 * 65 + 64 * 64 + 3 * 64) * (int)sizeof(float);
    cudaFuncSetAttribute(attn_kernel, cudaFuncAttributeMaxDynamicSharedMemorySize, asmem);
    attn_kernel<<<dim3(32, H_, B_), 256, asmem>>>(present, ctx);

    // output projection: out = ctx @ Wo + bo
    split_kernel<<<nsplit, 256>>>(ctx, ahi, alo);
    tsplit_kernel<<<tgrid, 256>>>(Wo, bhi, blo);
    gemm_mma_kernel<<<ggrid, 256, GEMM_SMEM>>>(ahi, alo, bhi, blo, bo, out,
                                               (long)S_ * D_, (long)D_, (long)DH_);
}

// round 4
// speedup vs baseline: 3.1149x; 1.8592x over previous
#include <cuda_runtime.h>
#include <cuda_bf16.h>
#include <cstdint>

#define B_  2
#define S_  2048
#define D_  1024
#define H_  16
#define DH_ 64

// ---------------------------------------------------------------------------
// Scratch (device globals — no allocation allowed)
// ---------------------------------------------------------------------------
__device__ __nv_bfloat16 g_ahi[(size_t)4096 * 1024]; // bf16-hi of GEMM A operand
__device__ __nv_bfloat16 g_alo[(size_t)4096 * 1024]; // bf16-lo
__device__ __nv_bfloat16 g_bhi[(size_t)1024 * 1024]; // bf16-hi of W^T [N,K]
__device__ __nv_bfloat16 g_blo[(size_t)1024 * 1024]; // bf16-lo
// bf16 hi/lo copies of projected Q/K/V in [B,H,S,DH]
__device__ __nv_bfloat16 g_qbh[(size_t)B_ * H_ * S_ * DH_];
__device__ __nv_bfloat16 g_qbl[(size_t)B_ * H_ * S_ * DH_];
__device__ __nv_bfloat16 g_kbh[(size_t)B_ * H_ * S_ * DH_];
__device__ __nv_bfloat16 g_kbl[(size_t)B_ * H_ * S_ * DH_];
__device__ __nv_bfloat16 g_vbh[(size_t)B_ * H_ * S_ * DH_];
__device__ __nv_bfloat16 g_vbl[(size_t)B_ * H_ * S_ * DH_];

// ---------------------------------------------------------------------------
__device__ __forceinline__ uint32_t smem_u32(const void* p) {
    uint32_t a;
    asm("{ .reg .u64 t; cvta.to.shared.u64 t, %1; cvt.u32.u64 %0, t; }" : "=r"(a) : "l"(p));
    return a;
}

#define LDMX4(r, addr) \
    asm volatile("ldmatrix.sync.aligned.m8n8.x4.shared.b16 {%0,%1,%2,%3}, [%4];" \
        : "=r"((r)[0]), "=r"((r)[1]), "=r"((r)[2]), "=r"((r)[3]) : "r"(addr))

#define LDMX4T(r, addr) \
    asm volatile("ldmatrix.sync.aligned.m8n8.x4.trans.shared.b16 {%0,%1,%2,%3}, [%4];" \
        : "=r"((r)[0]), "=r"((r)[1]), "=r"((r)[2]), "=r"((r)[3]) : "r"(addr))

#define MMA_BF16(d, a, b0, b1) \
    asm volatile("mma.sync.aligned.m16n8k16.row.col.f32.bf16.bf16.f32 " \
        "{%0,%1,%2,%3}, {%4,%5,%6,%7}, {%8,%9}, {%0,%1,%2,%3};" \
        : "+f"((d)[0]), "+f"((d)[1]), "+f"((d)[2]), "+f"((d)[3]) \
        : "r"((a)[0]), "r"((a)[1]), "r"((a)[2]), "r"((a)[3]), "r"(b0), "r"(b1))

#define CP_ASYNC16(sa, gp) \
    asm volatile("cp.async.cg.shared.global [%0], [%1], 16;" :: "r"(sa), "l"(gp))
#define CP_COMMIT() asm volatile("cp.async.commit_group;" ::: "memory")
#define CP_WAIT1()  asm volatile("cp.async.wait_group 1;" ::: "memory")
#define CP_WAIT0()  asm volatile("cp.async.wait_group 0;" ::: "memory")

__device__ __forceinline__ void pack_hl(float v0, float v1, uint32_t& hi, uint32_t& lo) {
    __nv_bfloat162 h2 = __floats2bfloat162_rn(v0, v1);
    __nv_bfloat162 l2 = __floats2bfloat162_rn(v0 - __bfloat162float(h2.x),
                                              v1 - __bfloat162float(h2.y));
    hi = *reinterpret_cast<uint32_t*>(&h2);
    lo = *reinterpret_cast<uint32_t*>(&l2);
}

// ---------------------------------------------------------------------------
// Prep: elementwise bf16 hi/lo split (X rows already K-major)
// ---------------------------------------------------------------------------
__global__ __launch_bounds__(256) void split_kernel(
    const float* __restrict__ x, __nv_bfloat16* __restrict__ hi,
    __nv_bfloat16* __restrict__ lo)
{
    int i = blockIdx.x * 256 + threadIdx.x;
    float4 v = ((const float4*)x)[i];
    uint32_t h0, l0, h1, l1;
    pack_hl(v.x, v.y, h0, l0);
    pack_hl(v.z, v.w, h1, l1);
    ((uint32_t*)hi)[i * 2]     = h0;
    ((uint32_t*)hi)[i * 2 + 1] = h1;
    ((uint32_t*)lo)[i * 2]     = l0;
    ((uint32_t*)lo)[i * 2 + 1] = l1;
}

// Prep: transpose [K,N] -> [N,K] with bf16 split (W -> W^T hi/lo)
__global__ __launch_bounds__(256) void tsplit_kernel(
    const float* __restrict__ W, __nv_bfloat16* __restrict__ th,
    __nv_bfloat16* __restrict__ tl)
{
    __shared__ float ts[32][33];
    int tx = threadIdx.x & 31, ty = threadIdx.x >> 5;
    int kb = blockIdx.x * 32, nb = blockIdx.y * 32;
    #pragma unroll
    for (int j = 0; j < 4; j++)
        ts[ty + j * 8][tx] = W[(size_t)(kb + ty + j * 8) * 1024 + nb + tx];
    __syncthreads();
    #pragma unroll
    for (int j = 0; j < 4; j++) {
        int n = nb + ty + j * 8, k = kb + tx;
        float v = ts[tx][ty + j * 8];
        __nv_bfloat16 h = __float2bfloat16(v);
        th[(size_t)n * 1024 + k] = h;
        tl[(size_t)n * 1024 + k] = __float2bfloat16(v - __bfloat162float(h));
    }
}

// ---------------------------------------------------------------------------
// bf16x3 mma.sync GEMM: out = X[4096,1024] @ W[1024,1024] + bias
// fp32 scatter (optional): idx = b*sB + s*sS + h*sH + d
// bf16 hi/lo scatter (optional): [B,H,S,DH] layout
// ---------------------------------------------------------------------------
#define SA_STRIDE 80
#define MAT_BYTES (128 * SA_STRIDE)
#define STG_BYTES (4 * MAT_BYTES)
#define GEMM_SMEM (2 * STG_BYTES)

__global__ __launch_bounds__(256) void gemm_mma_kernel(
    const __nv_bfloat16* __restrict__ Ahi, const __nv_bfloat16* __restrict__ Alo,
    const __nv_bfloat16* __restrict__ Bhi, const __nv_bfloat16* __restrict__ Blo,
    const float* __restrict__ bias, float* __restrict__ out,
    long sB, long sS, long sH,
    __nv_bfloat16* __restrict__ outh, __nv_bfloat16* __restrict__ outl)
{
    extern __shared__ char sm[];
    const uint32_t sbase = smem_u32(sm);
    const int tid = threadIdx.x, lane = tid & 31, wid = tid >> 5;
    const int wm = wid & 1, wn = wid >> 1;
    const int m0 = blockIdx.y * 128, n0 = blockIdx.x * 128;

    float acc[4][4][4] = {};

    const int arow  = lane & 15;
    const int akoff = (lane >> 4) * 16;
    const int brow  = ((lane >> 4) << 3) | (lane & 7);
    const int bkoff = ((lane >> 3) & 1) * 16;

    #define ISSUE(t) do { \
        const int k0i = (t) * 32; \
        const uint32_t sdst = sbase + ((t) & 1) * STG_BYTES; \
        _Pragma("unroll") \
        for (int i = 0; i < 8; i++) { \
            int idx = tid + i * 256; \
            int mat = idx >> 9, chunk = idx & 511; \
            int row = chunk >> 2, c = chunk & 3; \
            const __nv_bfloat16* gp; \
            if (mat == 0)      gp = Ahi + (size_t)(m0 + row) * 1024 + k0i + c * 8; \
            else if (mat == 1) gp = Alo + (size_t)(m0 + row) * 1024 + k0i + c * 8; \
            else if (mat == 2) gp = Bhi + (size_t)(n0 + row) * 1024 + k0i + c * 8; \
            else               gp = Blo + (size_t)(n0 + row) * 1024 + k0i + c * 8; \
            uint32_t sa = sdst + mat * MAT_BYTES + row * SA_STRIDE + c * 16; \
            CP_ASYNC16(sa, gp); \
        } \
        CP_COMMIT(); \
    } while (0)

    ISSUE(0);

    for (int t = 0; t < 32; t++) {
        if (t < 31) { ISSUE(t + 1); CP_WAIT1(); }
        else        { CP_WAIT0(); }
        __syncthreads();

        const uint32_t s0  = sbase + (t & 1) * STG_BYTES;
        const uint32_t pAh = s0;
        const uint32_t pAl = s0 + MAT_BYTES;
        const uint32_t pBh = s0 + 2 * MAT_BYTES;
        const uint32_t pBl = s0 + 3 * MAT_BYTES;

        #pragma unroll
        for (int ks = 0; ks < 2; ks++) {
            uint32_t ah[4][4], al[4][4];
            #pragma unroll
            for (int mf = 0; mf < 4; mf++) {
                uint32_t ra = (uint32_t)(wm * 64 + mf * 16 + arow) * SA_STRIDE + ks * 32 + akoff;
                LDMX4(ah[mf], pAh + ra);
                LDMX4(al[mf], pAl + ra);
            }
            uint32_t bh[2][4], bl[2][4];
            #pragma unroll
            for (int ng = 0; ng < 2; ng++) {
                uint32_t rb = (uint32_t)(wn * 32 + ng * 16 + brow) * SA_STRIDE + ks * 32 + bkoff;
                LDMX4(bh[ng], pBh + rb);
                LDMX4(bl[ng], pBl + rb);
            }
            #pragma unroll
            for (int mf = 0; mf < 4; mf++) {
                #pragma unroll
                for (int nf = 0; nf < 4; nf++) {
                    const uint32_t* bhp = &bh[nf >> 1][(nf & 1) * 2];
                    const uint32_t* blp = &bl[nf >> 1][(nf & 1) * 2];
                    MMA_BF16(acc[mf][nf], ah[mf], bhp[0], bhp[1]);
                    MMA_BF16(acc[mf][nf], ah[mf], blp[0], blp[1]);
                    MMA_BF16(acc[mf][nf], al[mf], bhp[0], bhp[1]);
                }
            }
        }
        __syncthreads();
    }

    // ---- epilogue ----
    const int g = lane >> 2, tig = lane & 3;
    const long s2S = DH_, s2H = (long)S_ * DH_, s2B = (long)H_ * S_ * DH_;
    #pragma unroll
    for (int mf = 0; mf < 4; mf++) {
        const int mA = m0 + wm * 64 + mf * 16 + g;
        const int b1 = mA >> 11, s1 = mA & 2047;
        const int b2 = (mA + 8) >> 11, s2 = (mA + 8) & 2047;
        #pragma unroll
        for (int nf = 0; nf < 4; nf++) {
            const int n = n0 + wn * 32 + nf * 8 + tig * 2;
            const int h = n >> 6, d = n & 63;
            const float bv0 = __ldg(bias + n), bv1 = __ldg(bias + n + 1);
            float p0 = acc[mf][nf][0] + bv0, p1 = acc[mf][nf][1] + bv1;
            float p2 = acc[mf][nf][2] + bv0, p3 = acc[mf][nf][3] + bv1;
            if (out) {
                float2 lo_pair, hi_pair;
                lo_pair.x = p0; lo_pair.y = p1;
                hi_pair.x = p2; hi_pair.y = p3;
                *(float2*)(out + (size_t)b1 * sB + (size_t)s1 * sS + (size_t)h * sH + d) = lo_pair;
                *(float2*)(out + (size_t)b2 * sB + (size_t)s2 * sS + (size_t)h * sH + d) = hi_pair;
            }
            if (outh) {
                uint32_t h0, l0, h1, l1;
                pack_hl(p0, p1, h0, l0);
                pack_hl(p2, p3, h1, l1);
                size_t i1 = (size_t)b1 * s2B + (size_t)s1 * s2S + (size_t)h * s2H + d;
                size_t i2 = (size_t)b2 * s2B + (size_t)s2 * s2S + (size_t)h * s2H + d;
                *(uint32_t*)(outh + i1) = h0;
                *(uint32_t*)(outl + i1) = l0;
                *(uint32_t*)(outh + i2) = h1;
                *(uint32_t*)(outl + i2) = l1;
            }
        }
    }
    #undef ISSUE
}

// ---------------------------------------------------------------------------
// Tensor-core flash attention (bf16x3, causal).
// CTA = 128 queries x one (b,h). 4 warps, 32 rows each. 64-key tiles.
// Writes ctx directly as bf16 hi/lo into the GEMM A buffers (g_ahi/g_alo).
// ---------------------------------------------------------------------------
#define QT_BYTES  (128 * 144)     // 18432
#define KT_BYTES  (64 * 144)      // 9216
#define ATT_SMEM  (2 * QT_BYTES + 4 * KT_BYTES)   // 73728

__global__ __launch_bounds__(128) void attn_mma_kernel(
    const __nv_bfloat16* __restrict__ Qhg, const __nv_bfloat16* __restrict__ Qlg,
    const __nv_bfloat16* __restrict__ Khg, const __nv_bfloat16* __restrict__ Klg,
    const __nv_bfloat16* __restrict__ Vhg, const __nv_bfloat16* __restrict__ Vlg,
    __nv_bfloat16* __restrict__ Ohg, __nv_bfloat16* __restrict__ Olg)
{
    extern __shared__ char sm[];
    const uint32_t sb  = smem_u32(sm);
    const uint32_t sQh = sb,             sQl = sb + QT_BYTES;
    const uint32_t sKh = sb + 2*QT_BYTES,        sKl = sKh + KT_BYTES;
    const uint32_t sVh = sKl + KT_BYTES,         sVl = sVh + KT_BYTES;

    const int tid = threadIdx.x, lane = tid & 31, wid = tid >> 5;
    const int qblk = blockIdx.x, h = blockIdx.y, b = blockIdx.z;
    const int q0 = qblk * 128;
    const int wrow = wid * 32;
    const int g = lane >> 2, tig = lane & 3;

    const size_t hoff = ((size_t)(b * H_ + h) * S_) * DH_;
    const __nv_bfloat16* qh_p = Qhg + hoff + (size_t)q0 * DH_;
    const __nv_bfloat16* ql_p = Qlg + hoff + (size_t)q0 * DH_;
    const __nv_bfloat16* kh_p = Khg + hoff;
    const __nv_bfloat16* kl_p = Klg + hoff;
    const __nv_bfloat16* vh_p = Vhg + hoff;
    const __nv_bfloat16* vl_p = Vlg + hoff;

    // ---- Q tile load (2 mats x 128 rows x 8 chunks) ----
    #pragma unroll
    for (int i = 0; i < 16; i++) {
        int idx = tid + i * 128;
        int mat = idx >> 10, rem = idx & 1023, row = rem >> 3, c = rem & 7;
        const __nv_bfloat16* gp = (mat ? ql_p : qh_p) + row * 64 + c * 8;
        uint32_t sa = (mat ? sQl : sQh) + row * 144 + c * 16;
        CP_ASYNC16(sa, gp);
    }

    #define KV_ISSUE(k0v) do { \
        _Pragma("unroll") \
        for (int i = 0; i < 16; i++) { \
            int idx = tid + i * 128; \
            int mat = idx >> 9, rem = idx & 511, row = rem >> 3, c = rem & 7; \
            const __nv_bfloat16* gp; uint32_t sa; \
            if (mat == 0)      { gp = kh_p; sa = sKh; } \
            else if (mat == 1) { gp = kl_p; sa = sKl; } \
            else if (mat == 2) { gp = vh_p; sa = sVh; } \
            else               { gp = vl_p; sa = sVl; } \
            gp += (size_t)((k0v) + row) * 64 + c * 8; \
            sa += row * 144 + c * 16; \
            CP_ASYNC16(sa, gp); \
        } \
        CP_COMMIT(); \
    } while (0)

    KV_ISSUE(0);

    float o[2][8][4] = {};
    float m_run[2][2] = {{-1e30f, -1e30f}, {-1e30f, -1e30f}};
    float l_run[2][2] = {};

    const int ktmax = 2 * qblk + 1;

    for (int kt = 0; kt <= ktmax; kt++) {
        const int k0 = kt * 64;
        CP_WAIT0();
        __syncthreads();

        // ---- S = Q K^T (bf16x3) ----
        float s[2][8][4] = {};
        #pragma unroll
        for (int kc = 0; kc < 4; kc++) {
            uint32_t qh[2][4], ql[2][4];
            #pragma unroll
            for (int mf = 0; mf < 2; mf++) {
                uint32_t ra = (uint32_t)(wrow + mf * 16 + (lane & 15)) * 144
                              + kc * 32 + (lane >> 4) * 16;
                LDMX4(qh[mf], sQh + ra);
                LDMX4(ql[mf], sQl + ra);
            }
            #pragma unroll
            for (int ng = 0; ng < 4; ng++) {
                uint32_t rb = (uint32_t)(ng * 16 + ((lane >> 4) << 3) + (lane & 7)) * 144
                              + kc * 32 + ((lane >> 3) & 1) * 16;
                uint32_t bh[4], bl[4];
                LDMX4(bh, sKh + rb);
                LDMX4(bl, sKl + rb);
                #pragma unroll
                for (int mf = 0; mf < 2; mf++) {
                    MMA_BF16(s[mf][2*ng],   qh[mf], bh[0], bh[1]);
                    MMA_BF16(s[mf][2*ng],   qh[mf], bl[0], bl[1]);
                    MMA_BF16(s[mf][2*ng],   ql[mf], bh[0], bh[1]);
                    MMA_BF16(s[mf][2*ng+1], qh[mf], bh[2], bh[3]);
                    MMA_BF16(s[mf][2*ng+1], qh[mf], bl[2], bl[3]);
                    MMA_BF16(s[mf][2*ng+1], ql[mf], bh[2], bh[3]);
                }
            }
        }

        // ---- scale + causal mask ----
        const bool maskw = (k0 + 63) > (q0 + wrow);
        #pragma unroll
        for (int mf = 0; mf < 2; mf++)
            #pragma unroll
            for (int nf = 0; nf < 8; nf++)
                #pragma unroll
                for (int r = 0; r < 4; r++) {
                    float v = s[mf][nf][r] * 0.125f;
                    if (maskw) {
                        int qi = q0 + wrow + mf * 16 + g + ((r >= 2) ? 8 : 0);
                        int kj = k0 + nf * 8 + tig * 2 + (r & 1);
                        if (kj > qi) v = -10000.f;
                    }
                    s[mf][nf][r] = v;
                }

        // ---- online softmax (per row-half: regs {0,1} row g, {2,3} row g+8) ----
        float alpha[2][2];
        #pragma unroll
        for (int mf = 0; mf < 2; mf++)
            #pragma unroll
            for (int h2 = 0; h2 < 2; h2++) {
                float mx = -1e30f;
                #pragma unroll
                for (int nf = 0; nf < 8; nf++)
                    mx = fmaxf(mx, fmaxf(s[mf][nf][h2*2], s[mf][nf][h2*2+1]));
                mx = fmaxf(mx, __shfl_xor_sync(0xffffffffu, mx, 1));
                mx = fmaxf(mx, __shfl_xor_sync(0xffffffffu, mx, 2));
                float mn = fmaxf(m_run[mf][h2], mx);
                float sum = 0.f;
                #pragma unroll
                for (int nf = 0; nf < 8; nf++) {
                    float p0 = __expf(s[mf][nf][h2*2]   - mn);
                    float p1 = __expf(s[mf][nf][h2*2+1] - mn);
                    s[mf][nf][h2*2]   = p0;
                    s[mf][nf][h2*2+1] = p1;
                    sum += p0 + p1;
                }
                sum += __shfl_xor_sync(0xffffffffu, sum, 1);
                sum += __shfl_xor_sync(0xffffffffu, sum, 2);
                float a = __expf(m_run[mf][h2] - mn);
                alpha[mf][h2] = a;
                m_run[mf][h2] = mn;
                l_run[mf][h2] = l_run[mf][h2] * a + sum;
            }

        // rescale O
        #pragma unroll
        for (int mf = 0; mf < 2; mf++)
            #pragma unroll
            for (int nf = 0; nf < 8; nf++) {
                o[mf][nf][0] *= alpha[mf][0];
                o[mf][nf][1] *= alpha[mf][0];
                o[mf][nf][2] *= alpha[mf][1];
                o[mf][nf][3] *= alpha[mf][1];
            }

        // ---- O += P V (bf16x3) ----
        #pragma unroll
        for (int kc = 0; kc < 4; kc++) {
            uint32_t ph[2][4], pl[2][4];
            #pragma unroll
            for (int mf = 0; mf < 2; mf++) {
                pack_hl(s[mf][2*kc][0],   s[mf][2*kc][1],   ph[mf][0], pl[mf][0]);
                pack_hl(s[mf][2*kc][2],   s[mf][2*kc][3],   ph[mf][1], pl[mf][1]);
                pack_hl(s[mf][2*kc+1][0], s[mf][2*kc+1][1], ph[mf][2], pl[mf][2]);
                pack_hl(s[mf][2*kc+1][2], s[mf][2*kc+1][3], ph[mf][3], pl[mf][3]);
            }
            #pragma unroll
            for (int ng = 0; ng < 4; ng++) {
                uint32_t rv = (uint32_t)(kc * 16 + ((lane >> 3) & 1) * 8 + (lane & 7)) * 144
                              + ng * 32 + (lane >> 4) * 16;
                uint32_t vh[4], vl[4];
                LDMX4T(vh, sVh + rv);
                LDMX4T(vl, sVl + rv);
                #pragma unroll
                for (int mf = 0; mf < 2; mf++) {
                    MMA_BF16(o[mf][2*ng],   ph[mf], vh[0], vh[1]);
                    MMA_BF16(o[mf][2*ng],   ph[mf], vl[0], vl[1]);
                    MMA_BF16(o[mf][2*ng],   pl[mf], vh[0], vh[1]);
                    MMA_BF16(o[mf][2*ng+1], ph[mf], vh[2], vh[3]);
                    MMA_BF16(o[mf][2*ng+1], ph[mf], vl[2], vl[3]);
                    MMA_BF16(o[mf][2*ng+1], pl[mf], vh[2], vh[3]);
                }
            }
        }

        __syncthreads();
        if (kt < ktmax) KV_ISSUE(k0 + 64);
    }

    // ---- epilogue: ctx -> bf16 hi/lo into GEMM A buffers ----
    float inv[2][2];
    #pragma unroll
    for (int mf = 0; mf < 2; mf++) {
        inv[mf][0] = 1.f / l_run[mf][0];
        inv[mf][1] = 1.f / l_run[mf][1];
    }
    #pragma unroll
    for (int mf = 0; mf < 2; mf++) {
        const int r0 = q0 + wrow + mf * 16 + g;
        const size_t m1 = (size_t)b * 2048 + r0;
        const size_t m2 = m1 + 8;
        #pragma unroll
        for (int nf = 0; nf < 8; nf++) {
            const int col = h * 64 + nf * 8 + tig * 2;
            uint32_t h0, l0, h1, l1;
            pack_hl(o[mf][nf][0] * inv[mf][0], o[mf][nf][1] * inv[mf][0], h0, l0);
            pack_hl(o[mf][nf][2] * inv[mf][1], o[mf][nf][3] * inv[mf][1], h1, l1);
            *(uint32_t*)(Ohg + m1 * 1024 + col) = h0;
            *(uint32_t*)(Olg + m1 * 1024 + col) = l0;
            *(uint32_t*)(Ohg + m2 * 1024 + col) = h1;
            *(uint32_t*)(Olg + m2 * 1024 + col) = l1;
        }
    }
    #undef KV_ISSUE
}

// ---------------------------------------------------------------------------
extern "C" void kernel_launch(void* const* d_in, const int* in_sizes, int n_in,
                              void* d_out, int out_size)
{
    const float* q  = (const float*)d_in[0];
    const float* k  = (const float*)d_in[1];
    const float* v  = (const float*)d_in[2];
    const float* Wq = (const float*)d_in[4];
    const float* bq = (const float*)d_in[5];
    const float* Wk = (const float*)d_in[6];
    const float* bk = (const float*)d_in[7];
    const float* Wv = (const float*)d_in[8];
    const float* bv = (const float*)d_in[9];
    const float* Wo = (const float*)d_in[10];
    const float* bo = (const float*)d_in[11];

    float* out = (float*)d_out;                       // [B,S,D]
    float* present = out + (size_t)B_ * S_ * D_;      // [B,2,H,S,DH]

    __nv_bfloat16 *ahi, *alo, *bhi, *blo, *qbh, *qbl, *kbh, *kbl, *vbh, *vbl;
    cudaGetSymbolAddress((void**)&ahi, g_ahi);
    cudaGetSymbolAddress((void**)&alo, g_alo);
    cudaGetSymbolAddress((void**)&bhi, g_bhi);
    cudaGetSymbolAddress((void**)&blo, g_blo);
    cudaGetSymbolAddress((void**)&qbh, g_qbh);
    cudaGetSymbolAddress((void**)&qbl, g_qbl);
    cudaGetSymbolAddress((void**)&kbh, g_kbh);
    cudaGetSymbolAddress((void**)&kbl, g_kbl);
    cudaGetSymbolAddress((void**)&vbh, g_vbh);
    cudaGetSymbolAddress((void**)&vbl, g_vbl);

    const long sB_head = (long)H_ * S_ * DH_;
    const long sH_head = (long)S_ * DH_;

    cudaFuncSetAttribute(gemm_mma_kernel, cudaFuncAttributeMaxDynamicSharedMemorySize, GEMM_SMEM);
    cudaFuncSetAttribute(attn_mma_kernel, cudaFuncAttributeMaxDynamicSharedMemorySize, ATT_SMEM);

    const int nsplit = (4096 * 1024 / 4) / 256;
    dim3 tgrid(32, 32), ggrid(8, 32);

    // Q projection -> bf16 hi/lo only
    split_kernel<<<nsplit, 256>>>(q, ahi, alo);
    tsplit_kernel<<<tgrid, 256>>>(Wq, bhi, blo);
    gemm_mma_kernel<<<ggrid, 256, GEMM_SMEM>>>(ahi, alo, bhi, blo, bq, nullptr,
                                               0, 0, 0, qbh, qbl);
    // K projection -> present[:,0] fp32 + bf16 hi/lo
    split_kernel<<<nsplit, 256>>>(k, ahi, alo);
    tsplit_kernel<<<tgrid, 256>>>(Wk, bhi, blo);
    gemm_mma_kernel<<<ggrid, 256, GEMM_SMEM>>>(ahi, alo, bhi, blo, bk, present,
                                               2 * sB_head, (long)DH_, sH_head, kbh, kbl);
    // V projection -> present[:,1] fp32 + bf16 hi/lo
    split_kernel<<<nsplit, 256>>>(v, ahi, alo);
    tsplit_kernel<<<tgrid, 256>>>(Wv, bhi, blo);
    gemm_mma_kernel<<<ggrid, 256, GEMM_SMEM>>>(ahi, alo, bhi, blo, bv, present + (size_t)sB_head,
                                               2 * sB_head, (long)DH_, sH_head, vbh, vbl);

    // attention: ctx written as bf16 hi/lo directly into GEMM A buffers
    attn_mma_kernel<<<dim3(S_ / 128, H_, B_), 128, ATT_SMEM>>>(
        qbh, qbl, kbh, kbl, vbh, vbl, ahi, alo);

    // output projection: out = ctx @ Wo + bo (fp32 only)
    tsplit_kernel<<<tgrid, 256>>>(Wo, bhi, blo);
    gemm_mma_kernel<<<ggrid, 256, GEMM_SMEM>>>(ahi, alo, bhi, blo, bo, out,
                                               (long)S_ * D_, (long)D_, (long)DH_,
                                               nullptr, nullptr);
}

// round 5
// speedup vs baseline: 3.5202x; 1.1301x over previous
#include <cuda_runtime.h>
#include <cuda_bf16.h>
#include <cstdint>

#define B_  2
#define S_  2048
#define D_  1024
#define H_  16
#define DH_ 64

// ---------------------------------------------------------------------------
// Scratch (device globals — no allocation allowed)
// ---------------------------------------------------------------------------
__device__ __nv_bfloat16 g_xh[3][(size_t)4096 * 1024]; // bf16-hi of X (q,k,v); [0] reused for ctx
__device__ __nv_bfloat16 g_xl[3][(size_t)4096 * 1024]; // bf16-lo
__device__ __nv_bfloat16 g_wh[4][(size_t)1024 * 1024]; // bf16-hi of W^T (q,k,v,o)
__device__ __nv_bfloat16 g_wl[4][(size_t)1024 * 1024];
// bf16 hi/lo copies of projected Q/K/V in [B,H,S,DH]
__device__ __nv_bfloat16 g_qbh[(size_t)B_ * H_ * S_ * DH_];
__device__ __nv_bfloat16 g_qbl[(size_t)B_ * H_ * S_ * DH_];
__device__ __nv_bfloat16 g_kbh[(size_t)B_ * H_ * S_ * DH_];
__device__ __nv_bfloat16 g_kbl[(size_t)B_ * H_ * S_ * DH_];
__device__ __nv_bfloat16 g_vbh[(size_t)B_ * H_ * S_ * DH_];
__device__ __nv_bfloat16 g_vbl[(size_t)B_ * H_ * S_ * DH_];

// ---------------------------------------------------------------------------
__device__ __forceinline__ uint32_t smem_u32(const void* p) {
    uint32_t a;
    asm("{ .reg .u64 t; cvta.to.shared.u64 t, %1; cvt.u32.u64 %0, t; }" : "=r"(a) : "l"(p));
    return a;
}

#define LDMX4(r, addr) \
    asm volatile("ldmatrix.sync.aligned.m8n8.x4.shared.b16 {%0,%1,%2,%3}, [%4];" \
        : "=r"((r)[0]), "=r"((r)[1]), "=r"((r)[2]), "=r"((r)[3]) : "r"(addr))

#define LDMX4T(r, addr) \
    asm volatile("ldmatrix.sync.aligned.m8n8.x4.trans.shared.b16 {%0,%1,%2,%3}, [%4];" \
        : "=r"((r)[0]), "=r"((r)[1]), "=r"((r)[2]), "=r"((r)[3]) : "r"(addr))

#define MMA_BF16(d, a, b0, b1) \
    asm volatile("mma.sync.aligned.m16n8k16.row.col.f32.bf16.bf16.f32 " \
        "{%0,%1,%2,%3}, {%4,%5,%6,%7}, {%8,%9}, {%0,%1,%2,%3};" \
        : "+f"((d)[0]), "+f"((d)[1]), "+f"((d)[2]), "+f"((d)[3]) \
        : "r"((a)[0]), "r"((a)[1]), "r"((a)[2]), "r"((a)[3]), "r"(b0), "r"(b1))

#define CP_ASYNC16(sa, gp) \
    asm volatile("cp.async.cg.shared.global [%0], [%1], 16;" :: "r"(sa), "l"(gp))
#define CP_COMMIT() asm volatile("cp.async.commit_group;" ::: "memory")
#define CP_WAITN(n) asm volatile("cp.async.wait_group %0;" :: "n"(n) : "memory")

__device__ __forceinline__ void pack_hl(float v0, float v1, uint32_t& hi, uint32_t& lo) {
    __nv_bfloat162 h2 = __floats2bfloat162_rn(v0, v1);
    __nv_bfloat162 l2 = __floats2bfloat162_rn(v0 - __bfloat162float(h2.x),
                                              v1 - __bfloat162float(h2.y));
    hi = *reinterpret_cast<uint32_t*>(&h2);
    lo = *reinterpret_cast<uint32_t*>(&l2);
}

// ---------------------------------------------------------------------------
// Prep: fused elementwise bf16 hi/lo split for q,k,v (blockIdx.y selects)
// ---------------------------------------------------------------------------
__global__ __launch_bounds__(256) void split3_kernel(
    const float* __restrict__ x0, const float* __restrict__ x1,
    const float* __restrict__ x2,
    __nv_bfloat16* __restrict__ h0, __nv_bfloat16* __restrict__ l0,
    __nv_bfloat16* __restrict__ h1, __nv_bfloat16* __restrict__ l1,
    __nv_bfloat16* __restrict__ h2, __nv_bfloat16* __restrict__ l2)
{
    const int z = blockIdx.y;
    const float* x = (z == 0) ? x0 : (z == 1) ? x1 : x2;
    __nv_bfloat16* hi = (z == 0) ? h0 : (z == 1) ? h1 : h2;
    __nv_bfloat16* lo = (z == 0) ? l0 : (z == 1) ? l1 : l2;
    int i = blockIdx.x * 256 + threadIdx.x;
    float4 v = ((const float4*)x)[i];
    uint32_t a0, b0, a1, b1;
    pack_hl(v.x, v.y, a0, b0);
    pack_hl(v.z, v.w, a1, b1);
    ((uint32_t*)hi)[i * 2]     = a0;
    ((uint32_t*)hi)[i * 2 + 1] = a1;
    ((uint32_t*)lo)[i * 2]     = b0;
    ((uint32_t*)lo)[i * 2 + 1] = b1;
}

// Prep: fused transpose+split of all 4 weights (blockIdx.z selects)
__global__ __launch_bounds__(256) void tsplit4_kernel(
    const float* __restrict__ W0, const float* __restrict__ W1,
    const float* __restrict__ W2, const float* __restrict__ W3)
{
    const int z = blockIdx.z;
    const float* W = (z == 0) ? W0 : (z == 1) ? W1 : (z == 2) ? W2 : W3;
    __nv_bfloat16* th = g_wh[z];
    __nv_bfloat16* tl = g_wl[z];
    __shared__ float ts[32][33];
    int tx = threadIdx.x & 31, ty = threadIdx.x >> 5;
    int kb = blockIdx.x * 32, nb = blockIdx.y * 32;
    #pragma unroll
    for (int j = 0; j < 4; j++)
        ts[ty + j * 8][tx] = W[(size_t)(kb + ty + j * 8) * 1024 + nb + tx];
    __syncthreads();
    #pragma unroll
    for (int j = 0; j < 4; j++) {
        int n = nb + ty + j * 8, k = kb + tx;
        float v = ts[tx][ty + j * 8];
        __nv_bfloat16 h = __float2bfloat16(v);
        th[(size_t)n * 1024 + k] = h;
        tl[(size_t)n * 1024 + k] = __float2bfloat16(v - __bfloat162float(h));
    }
}

// ---------------------------------------------------------------------------
// bf16x3 mma.sync GEMM, batched over blockIdx.z via a param struct.
// out (fp32, optional): idx = b*sB + s*sS + h*sH + d
// oh/ol (bf16 hi/lo, optional): [B,H,S,DH] layout
// ---------------------------------------------------------------------------
struct GB {
    const __nv_bfloat16 *Ah, *Al, *Bh, *Bl;
    const float* bias;
    float* out; long sB, sS, sH;
    __nv_bfloat16 *oh, *ol;
};
struct GB3 { GB g[3]; };

#define SA_STRIDE 80
#define MAT_BYTES (128 * SA_STRIDE)
#define STG_BYTES (4 * MAT_BYTES)
#define GEMM_SMEM (2 * STG_BYTES)

__global__ __launch_bounds__(256) void gemm_mma_kernel(GB3 P)
{
    const GB p = P.g[blockIdx.z];
    extern __shared__ char sm[];
    const uint32_t sbase = smem_u32(sm);
    const int tid = threadIdx.x, lane = tid & 31, wid = tid >> 5;
    const int wm = wid & 1, wn = wid >> 1;
    const int m0 = blockIdx.y * 128, n0 = blockIdx.x * 128;

    float acc[4][4][4] = {};

    const int arow  = lane & 15;
    const int akoff = (lane >> 4) * 16;
    const int brow  = ((lane >> 4) << 3) | (lane & 7);
    const int bkoff = ((lane >> 3) & 1) * 16;

    #define ISSUE(t) do { \
        const int k0i = (t) * 32; \
        const uint32_t sdst = sbase + ((t) & 1) * STG_BYTES; \
        _Pragma("unroll") \
        for (int i = 0; i < 8; i++) { \
            int idx = tid + i * 256; \
            int mat = idx >> 9, chunk = idx & 511; \
            int row = chunk >> 2, c = chunk & 3; \
            const __nv_bfloat16* gp; \
            if (mat == 0)      gp = p.Ah + (size_t)(m0 + row) * 1024 + k0i + c * 8; \
            else if (mat == 1) gp = p.Al + (size_t)(m0 + row) * 1024 + k0i + c * 8; \
            else if (mat == 2) gp = p.Bh + (size_t)(n0 + row) * 1024 + k0i + c * 8; \
            else               gp = p.Bl + (size_t)(n0 + row) * 1024 + k0i + c * 8; \
            uint32_t sa = sdst + mat * MAT_BYTES + row * SA_STRIDE + c * 16; \
            CP_ASYNC16(sa, gp); \
        } \
        CP_COMMIT(); \
    } while (0)

    ISSUE(0);

    for (int t = 0; t < 32; t++) {
        if (t < 31) { ISSUE(t + 1); CP_WAITN(1); }
        else        { CP_WAITN(0); }
        __syncthreads();

        const uint32_t s0  = sbase + (t & 1) * STG_BYTES;
        const uint32_t pAh = s0;
        const uint32_t pAl = s0 + MAT_BYTES;
        const uint32_t pBh = s0 + 2 * MAT_BYTES;
        const uint32_t pBl = s0 + 3 * MAT_BYTES;

        #pragma unroll
        for (int ks = 0; ks < 2; ks++) {
            uint32_t ah[4][4], al[4][4];
            #pragma unroll
            for (int mf = 0; mf < 4; mf++) {
                uint32_t ra = (uint32_t)(wm * 64 + mf * 16 + arow) * SA_STRIDE + ks * 32 + akoff;
                LDMX4(ah[mf], pAh + ra);
                LDMX4(al[mf], pAl + ra);
            }
            uint32_t bh[2][4], bl[2][4];
            #pragma unroll
            for (int ng = 0; ng < 2; ng++) {
                uint32_t rb = (uint32_t)(wn * 32 + ng * 16 + brow) * SA_STRIDE + ks * 32 + bkoff;
                LDMX4(bh[ng], pBh + rb);
                LDMX4(bl[ng], pBl + rb);
            }
            #pragma unroll
            for (int mf = 0; mf < 4; mf++) {
                #pragma unroll
                for (int nf = 0; nf < 4; nf++) {
                    const uint32_t* bhp = &bh[nf >> 1][(nf & 1) * 2];
                    const uint32_t* blp = &bl[nf >> 1][(nf & 1) * 2];
                    MMA_BF16(acc[mf][nf], ah[mf], bhp[0], bhp[1]);
                    MMA_BF16(acc[mf][nf], ah[mf], blp[0], blp[1]);
                    MMA_BF16(acc[mf][nf], al[mf], bhp[0], bhp[1]);
                }
            }
        }
        __syncthreads();
    }

    // ---- epilogue ----
    const int g = lane >> 2, tig = lane & 3;
    const long s2S = DH_, s2H = (long)S_ * DH_, s2B = (long)H_ * S_ * DH_;
    #pragma unroll
    for (int mf = 0; mf < 4; mf++) {
        const int mA = m0 + wm * 64 + mf * 16 + g;
        const int b1 = mA >> 11, s1 = mA & 2047;
        const int b2 = (mA + 8) >> 11, s2 = (mA + 8) & 2047;
        #pragma unroll
        for (int nf = 0; nf < 4; nf++) {
            const int n = n0 + wn * 32 + nf * 8 + tig * 2;
            const int h = n >> 6, d = n & 63;
            const float bv0 = __ldg(p.bias + n), bv1 = __ldg(p.bias + n + 1);
            float p0 = acc[mf][nf][0] + bv0, p1 = acc[mf][nf][1] + bv1;
            float p2 = acc[mf][nf][2] + bv0, p3 = acc[mf][nf][3] + bv1;
            if (p.out) {
                float2 lo_pair, hi_pair;
                lo_pair.x = p0; lo_pair.y = p1;
                hi_pair.x = p2; hi_pair.y = p3;
                *(float2*)(p.out + (size_t)b1 * p.sB + (size_t)s1 * p.sS + (size_t)h * p.sH + d) = lo_pair;
                *(float2*)(p.out + (size_t)b2 * p.sB + (size_t)s2 * p.sS + (size_t)h * p.sH + d) = hi_pair;
            }
            if (p.oh) {
                uint32_t h0, l0, h1, l1;
                pack_hl(p0, p1, h0, l0);
                pack_hl(p2, p3, h1, l1);
                size_t i1 = (size_t)b1 * s2B + (size_t)s1 * s2S + (size_t)h * s2H + d;
                size_t i2 = (size_t)b2 * s2B + (size_t)s2 * s2S + (size_t)h * s2H + d;
                *(uint32_t*)(p.oh + i1) = h0;
                *(uint32_t*)(p.ol + i1) = l0;
                *(uint32_t*)(p.oh + i2) = h1;
                *(uint32_t*)(p.ol + i2) = l1;
            }
        }
    }
    #undef ISSUE
}

// ---------------------------------------------------------------------------
// Tensor-core flash attention (bf16x3, causal).
// 128 queries/CTA, 4 warps. Q fragments hoisted to registers.
// KV double-buffered: next tile's cp.async issued before compute.
// Flat grid, biggest q-blocks launched first.
// ---------------------------------------------------------------------------
#define QT_BYTES   (128 * 144)          // per Q mat: 18432
#define KVMAT      (64 * 144)           // 9216
#define KVSTG      (4 * KVMAT)          // 36864
#define ATT_SMEM   (2 * QT_BYTES + 2 * KVSTG)   // 110592

__global__ __launch_bounds__(128) void attn_mma_kernel(
    const __nv_bfloat16* __restrict__ Qhg, const __nv_bfloat16* __restrict__ Qlg,
    const __nv_bfloat16* __restrict__ Khg, const __nv_bfloat16* __restrict__ Klg,
    const __nv_bfloat16* __restrict__ Vhg, const __nv_bfloat16* __restrict__ Vlg,
    __nv_bfloat16* __restrict__ Ohg, __nv_bfloat16* __restrict__ Olg)
{
    extern __shared__ char sm[];
    const uint32_t sb  = smem_u32(sm);
    const uint32_t sQh = sb, sQl = sb + QT_BYTES;
    const uint32_t sKV = sb + 2 * QT_BYTES;

    const int tid = threadIdx.x, lane = tid & 31, wid = tid >> 5;
    const int bidx = blockIdx.x;
    const int qblk = (S_ / 128 - 1) - (bidx >> 5);   // biggest first
    const int hb = bidx & 31;
    const int h = hb & 15, b = hb >> 4;
    const int q0 = qblk * 128;
    const int wrow = wid * 32;
    const int g = lane >> 2, tig = lane & 3;

    const size_t hoff = ((size_t)(b * H_ + h) * S_) * DH_;
    const __nv_bfloat16* qh_p = Qhg + hoff + (size_t)q0 * DH_;
    const __nv_bfloat16* ql_p = Qlg + hoff + (size_t)q0 * DH_;
    const __nv_bfloat16* kh_p = Khg + hoff;
    const __nv_bfloat16* kl_p = Klg + hoff;
    const __nv_bfloat16* vh_p = Vhg + hoff;
    const __nv_bfloat16* vl_p = Vlg + hoff;

    #define KV_ISSUE(k0v, st) do { \
        const uint32_t sst = sKV + (st) * KVSTG; \
        _Pragma("unroll") \
        for (int i = 0; i < 16; i++) { \
            int idx = tid + i * 128; \
            int mat = idx >> 9, rem = idx & 511, row = rem >> 3, c = rem & 7; \
            const __nv_bfloat16* gp; uint32_t sa; \
            if (mat == 0)      { gp = kh_p; sa = sst; } \
            else if (mat == 1) { gp = kl_p; sa = sst + KVMAT; } \
            else if (mat == 2) { gp = vh_p; sa = sst + 2 * KVMAT; } \
            else               { gp = vl_p; sa = sst + 3 * KVMAT; } \
            gp += (size_t)((k0v) + row) * 64 + c * 8; \
            sa += row * 144 + c * 16; \
            CP_ASYNC16(sa, gp); \
        } \
        CP_COMMIT(); \
    } while (0)

    const int ktmax = 2 * qblk + 1;

    // ---- prologue: Q + KV0 (group A), KV1 (group B) ----
    #pragma unroll
    for (int i = 0; i < 16; i++) {
        int idx = tid + i * 128;
        int mat = idx >> 10, rem = idx & 1023, row = rem >> 3, c = rem & 7;
        const __nv_bfloat16* gp = (mat ? ql_p : qh_p) + row * 64 + c * 8;
        uint32_t sa = (mat ? sQl : sQh) + row * 144 + c * 16;
        CP_ASYNC16(sa, gp);
    }
    KV_ISSUE(0, 0);                 // commits Q+KV0 together
    if (ktmax >= 1) KV_ISSUE(64, 1);
    if (ktmax >= 1) { CP_WAITN(1); } else { CP_WAITN(0); }
    __syncthreads();

    // ---- hoist Q fragments ----
    uint32_t qfh[4][2][4], qfl[4][2][4];
    #pragma unroll
    for (int kc = 0; kc < 4; kc++)
        #pragma unroll
        for (int mf = 0; mf < 2; mf++) {
            uint32_t ra = (uint32_t)(wrow + mf * 16 + (lane & 15)) * 144
                          + kc * 32 + (lane >> 4) * 16;
            LDMX4(qfh[kc][mf], sQh + ra);
            LDMX4(qfl[kc][mf], sQl + ra);
        }

    float o[2][8][4] = {};
    float m_run[2][2] = {{-1e30f, -1e30f}, {-1e30f, -1e30f}};
    float l_run[2][2] = {};

    for (int kt = 0; kt <= ktmax; kt++) {
        const int k0 = kt * 64;
        const uint32_t sst = sKV + (kt & 1) * KVSTG;
        const uint32_t sKh = sst, sKl = sst + KVMAT;
        const uint32_t sVh = sst + 2 * KVMAT, sVl = sst + 3 * KVMAT;

        // ---- S = Q K^T (bf16x3) ----
        float s[2][8][4] = {};
        #pragma unroll
        for (int kc = 0; kc < 4; kc++) {
            #pragma unroll
            for (int ng = 0; ng < 4; ng++) {
                uint32_t rb = (uint32_t)(ng * 16 + ((lane >> 4) << 3) + (lane & 7)) * 144
                              + kc * 32 + ((lane >> 3) & 1) * 16;
                uint32_t bh[4], bl[4];
                LDMX4(bh, sKh + rb);
                LDMX4(bl, sKl + rb);
                #pragma unroll
                for (int mf = 0; mf < 2; mf++) {
                    MMA_BF16(s[mf][2*ng],   qfh[kc][mf], bh[0], bh[1]);
                    MMA_BF16(s[mf][2*ng],   qfh[kc][mf], bl[0], bl[1]);
                    MMA_BF16(s[mf][2*ng],   qfl[kc][mf], bh[0], bh[1]);
                    MMA_BF16(s[mf][2*ng+1], qfh[kc][mf], bh[2], bh[3]);
                    MMA_BF16(s[mf][2*ng+1], qfh[kc][mf], bl[2], bl[3]);
                    MMA_BF16(s[mf][2*ng+1], qfl[kc][mf], bh[2], bh[3]);
                }
            }
        }

        // ---- scale + causal mask ----
        const bool maskw = (k0 + 63) > (q0 + wrow);
        #pragma unroll
        for (int mf = 0; mf < 2; mf++)
            #pragma unroll
            for (int nf = 0; nf < 8; nf++)
                #pragma unroll
                for (int r = 0; r < 4; r++) {
                    float v = s[mf][nf][r] * 0.125f;
                    if (maskw) {
                        int qi = q0 + wrow + mf * 16 + g + ((r >= 2) ? 8 : 0);
                        int kj = k0 + nf * 8 + tig * 2 + (r & 1);
                        if (kj > qi) v = -10000.f;
                    }
                    s[mf][nf][r] = v;
                }

        // ---- online softmax ----
        float alpha[2][2];
        #pragma unroll
        for (int mf = 0; mf < 2; mf++)
            #pragma unroll
            for (int h2 = 0; h2 < 2; h2++) {
                float mx = -1e30f;
                #pragma unroll
                for (int nf = 0; nf < 8; nf++)
                    mx = fmaxf(mx, fmaxf(s[mf][nf][h2*2], s[mf][nf][h2*2+1]));
                mx = fmaxf(mx, __shfl_xor_sync(0xffffffffu, mx, 1));
                mx = fmaxf(mx, __shfl_xor_sync(0xffffffffu, mx, 2));
                float mn = fmaxf(m_run[mf][h2], mx);
                float sum = 0.f;
                #pragma unroll
                for (int nf = 0; nf < 8; nf++) {
                    float p0 = __expf(s[mf][nf][h2*2]   - mn);
                    float p1 = __expf(s[mf][nf][h2*2+1] - mn);
                    s[mf][nf][h2*2]   = p0;
                    s[mf][nf][h2*2+1] = p1;
                    sum += p0 + p1;
                }
                sum += __shfl_xor_sync(0xffffffffu, sum, 1);
                sum += __shfl_xor_sync(0xffffffffu, sum, 2);
                float a = __expf(m_run[mf][h2] - mn);
                alpha[mf][h2] = a;
                m_run[mf][h2] = mn;
                l_run[mf][h2] = l_run[mf][h2] * a + sum;
            }

        #pragma unroll
        for (int mf = 0; mf < 2; mf++)
            #pragma unroll
            for (int nf = 0; nf < 8; nf++) {
                o[mf][nf][0] *= alpha[mf][0];
                o[mf][nf][1] *= alpha[mf][0];
                o[mf][nf][2] *= alpha[mf][1];
                o[mf][nf][3] *= alpha[mf][1];
            }

        // ---- O += P V (bf16x3) ----
        #pragma unroll
        for (int kc = 0; kc < 4; kc++) {
            uint32_t ph[2][4], pl[2][4];
            #pragma unroll
            for (int mf = 0; mf < 2; mf++) {
                pack_hl(s[mf][2*kc][0],   s[mf][2*kc][1],   ph[mf][0], pl[mf][0]);
                pack_hl(s[mf][2*kc][2],   s[mf][2*kc][3],   ph[mf][1], pl[mf][1]);
                pack_hl(s[mf][2*kc+1][0], s[mf][2*kc+1][1], ph[mf][2], pl[mf][2]);
                pack_hl(s[mf][2*kc+1][2], s[mf][2*kc+1][3], ph[mf][3], pl[mf][3]);
            }
            #pragma unroll
            for (int ng = 0; ng < 4; ng++) {
                uint32_t rv = (uint32_t)(kc * 16 + ((lane >> 3) & 1) * 8 + (lane & 7)) * 144
                              + ng * 32 + (lane >> 4) * 16;
                uint32_t vh[4], vl[4];
                LDMX4T(vh, sVh + rv);
                LDMX4T(vl, sVl + rv);
                #pragma unroll
                for (int mf = 0; mf < 2; mf++) {
                    MMA_BF16(o[mf][2*ng],   ph[mf], vh[0], vh[1]);
                    MMA_BF16(o[mf][2*ng],   ph[mf], vl[0], vl[1]);
                    MMA_BF16(o[mf][2*ng],   pl[mf], vh[0], vh[1]);
                    MMA_BF16(o[mf][2*ng+1], ph[mf], vh[2], vh[3]);
                    MMA_BF16(o[mf][2*ng+1], ph[mf], vl[2], vl[3]);
                    MMA_BF16(o[mf][2*ng+1], pl[mf], vh[2], vh[3]);
                }
            }
        }

        __syncthreads();                       // all warps done reading stage kt&1
        if (kt + 2 <= ktmax) KV_ISSUE(k0 + 128, kt & 1);
        if (kt < ktmax) {
            if (kt + 2 <= ktmax) { CP_WAITN(1); } else { CP_WAITN(0); }
            __syncthreads();                   // KV(kt+1) visible to all
        }
    }

    // ---- epilogue: ctx -> bf16 hi/lo into GEMM A buffers ----
    float inv[2][2];
    #pragma unroll
    for (int mf = 0; mf < 2; mf++) {
        inv[mf][0] = 1.f / l_run[mf][0];
        inv[mf][1] = 1.f / l_run[mf][1];
    }
    #pragma unroll
    for (int mf = 0; mf < 2; mf++) {
        const int r0 = q0 + wrow + mf * 16 + g;
        const size_t m1 = (size_t)b * 2048 + r0;
        const size_t m2 = m1 + 8;
        #pragma unroll
        for (int nf = 0; nf < 8; nf++) {
            const int col = h * 64 + nf * 8 + tig * 2;
            uint32_t h0, l0, h1, l1;
            pack_hl(o[mf][nf][0] * inv[mf][0], o[mf][nf][1] * inv[mf][0], h0, l0);
            pack_hl(o[mf][nf][2] * inv[mf][1], o[mf][nf][3] * inv[mf][1], h1, l1);
            *(uint32_t*)(Ohg + m1 * 1024 + col) = h0;
            *(uint32_t*)(Olg + m1 * 1024 + col) = l0;
            *(uint32_t*)(Ohg + m2 * 1024 + col) = h1;
            *(uint32_t*)(Olg + m2 * 1024 + col) = l1;
        }
    }
    #undef KV_ISSUE
}

// ---------------------------------------------------------------------------
extern "C" void kernel_launch(void* const* d_in, const int* in_sizes, int n_in,
                              void* d_out, int out_size)
{
    const float* q  = (const float*)d_in[0];
    const float* k  = (const float*)d_in[1];
    const float* v  = (const float*)d_in[2];
    const float* Wq = (const float*)d_in[4];
    const float* bq = (const float*)d_in[5];
    const float* Wk = (const float*)d_in[6];
    const float* bk = (const float*)d_in[7];
    const float* Wv = (const float*)d_in[8];
    const float* bv = (const float*)d_in[9];
    const float* Wo = (const float*)d_in[10];
    const float* bo = (const float*)d_in[11];

    float* out = (float*)d_out;                       // [B,S,D]
    float* present = out + (size_t)B_ * S_ * D_;      // [B,2,H,S,DH]

    __nv_bfloat16 *xh0, *xl0, *xh1, *xl1, *xh2, *xl2;
    __nv_bfloat16 *wh0, *wl0, *wh1, *wl1, *wh2, *wl2, *wh3, *wl3;
    __nv_bfloat16 *qbh, *qbl, *kbh, *kbl, *vbh, *vbl;
    cudaGetSymbolAddress((void**)&xh0, g_xh);
    cudaGetSymbolAddress((void**)&xl0, g_xl);
    cudaGetSymbolAddress((void**)&wh0, g_wh);
    cudaGetSymbolAddress((void**)&wl0, g_wl);
    cudaGetSymbolAddress((void**)&qbh, g_qbh);
    cudaGetSymbolAddress((void**)&qbl, g_qbl);
    cudaGetSymbolAddress((void**)&kbh, g_kbh);
    cudaGetSymbolAddress((void**)&kbl, g_kbl);
    cudaGetSymbolAddress((void**)&vbh, g_vbh);
    cudaGetSymbolAddress((void**)&vbl, g_vbl);
    const size_t XSZ = (size_t)4096 * 1024, WSZ = (size_t)1024 * 1024;
    xh1 = xh0 + XSZ; xh2 = xh0 + 2 * XSZ;
    xl1 = xl0 + XSZ; xl2 = xl0 + 2 * XSZ;
    wh1 = wh0 + WSZ; wh2 = wh0 + 2 * WSZ; wh3 = wh0 + 3 * WSZ;
    wl1 = wl0 + WSZ; wl2 = wl0 + 2 * WSZ; wl3 = wl0 + 3 * WSZ;

    const long sB_head = (long)H_ * S_ * DH_;
    const long sH_head = (long)S_ * DH_;

    cudaFuncSetAttribute(gemm_mma_kernel, cudaFuncAttributeMaxDynamicSharedMemorySize, GEMM_SMEM);
    cudaFuncSetAttribute(attn_mma_kernel, cudaFuncAttributeMaxDynamicSharedMemorySize, ATT_SMEM);

    // prep: all 4 weight transposes, all 3 input splits
    tsplit4_kernel<<<dim3(32, 32, 4), 256>>>(Wq, Wk, Wv, Wo);
    split3_kernel<<<dim3(4096, 3), 256>>>(q, k, v, xh0, xl0, xh1, xl1, xh2, xl2);

    // fused Q/K/V projections
    GB3 P;
    P.g[0] = {xh0, xl0, wh0, wl0, bq, nullptr, 0, 0, 0, qbh, qbl};
    P.g[1] = {xh1, xl1, wh1, wl1, bk, present, 2 * sB_head, (long)DH_, sH_head, kbh, kbl};
    P.g[2] = {xh2, xl2, wh2, wl2, bv, present + (size_t)sB_head,
              2 * sB_head, (long)DH_, sH_head, vbh, vbl};
    gemm_mma_kernel<<<dim3(8, 32, 3), 256, GEMM_SMEM>>>(P);

    // attention: ctx written as bf16 hi/lo into g_xh[0]/g_xl[0]
    attn_mma_kernel<<<(S_ / 128) * H_ * B_, 128, ATT_SMEM>>>(
        qbh, qbl, kbh, kbl, vbh, vbl, xh0, xl0);

    // output projection: out = ctx @ Wo + bo
    GB3 PO;
    PO.g[0] = {xh0, xl0, wh3, wl3, bo, out, (long)S_ * D_, (long)D_, (long)DH_,
               nullptr, nullptr};
    PO.g[1] = PO.g[0];
    PO.g[2] = PO.g[0];
    gemm_mma_kernel<<<dim3(8, 32, 1), 256, GEMM_SMEM>>>(PO);
}